// round 1
// baseline (speedup 1.0000x reference)
#include <cuda_runtime.h>
#include <math.h>

// Problem constants (static per registry problem: D=192 grid, 96 samples/LOR)
#define D 192
#define S_SAMPLES 96
#define NWARP_PER_BLK 8

static __device__ __forceinline__ float kw_const() {
    // sqrt(3*3/pi)
    return 1.6925687506f;
}

// PERM: 0 = z-set (ix,iy,iz)->(ix,iy,iz)
//       1 = x-set (ix,iy,iz)->(iy,iz,ix)   [imgx = transpose(img,(2,0,1)), bpxt = transpose(bpx,(1,2,0))]
//       2 = y-set (ix,iy,iz)->(iy,ix,iz)   [imgy = transpose(img,(1,0,2)), bpyt = transpose(bpy,(1,0,2))]
template<int PERM>
static __device__ __forceinline__ int lin_idx(int ix, int iy, int iz) {
    if (PERM == 0) return (ix * D + iy) * D + iz;
    if (PERM == 1) return (iy * D + iz) * D + ix;
    return (iy * D + ix) * D + iz;
}

template<int PERM>
__global__ void __launch_bounds__(NWARP_PER_BLK * 32)
lor_kernel(const float* __restrict__ lors,   // [n,6]
           const float* __restrict__ img,    // [D,D,D] original layout
           const float* __restrict__ center, // [3]
           const float* __restrict__ size,   // [3]
           float* __restrict__ acc,          // [D,D,D] accumulation (original layout)
           int n)
{
    int warp = (blockIdx.x * blockDim.x + threadIdx.x) >> 5;
    int lane = threadIdx.x & 31;
    if (warp >= n) return;

    const float* L = lors + (size_t)warp * 6;
    float p1x = L[0], p1y = L[1], p1z = L[2];
    float p2x = L[3], p2y = L[4], p2z = L[5];

    float cx = center[0], cy = center[1], cz = center[2];
    float sx = size[0],   sy = size[1],   sz = size[2];

    // voxel size per axis and grid origin (matches reference arithmetic)
    float vszx = sx / (float)D, vszy = sy / (float)D, vszz = sz / (float)D;
    float ox = cx - 0.5f * sx, oy = cy - 0.5f * sy, oz = cz - 0.5f * sz;

    float dx = p2x - p1x, dy = p2y - p1y, dz = p2z - p1z;
    float seg = sqrtf(dx * dx + dy * dy + dz * dz) * (1.0f / (float)S_SAMPLES);

    // 3 samples per lane: s = lane, lane+32, lane+64
    float vX[3], vY[3], vZ[3];
    float sum = 0.0f;

    #pragma unroll
    for (int k = 0; k < 3; k++) {
        int s = lane + 32 * k;
        float t = ((float)s + 0.5f) * (1.0f / (float)S_SAMPLES);
        float px = p1x + t * dx;
        float py = p1y + t * dy;
        float pz = p1z + t * dz;
        float wx = (px - ox) / vszx - 0.5f;
        float wy = (py - oy) / vszy - 0.5f;
        float wz = (pz - oz) / vszz - 0.5f;
        vX[k] = wx; vY[k] = wy; vZ[k] = wz;

        float fx = floorf(wx), fy = floorf(wy), fz = floorf(wz);
        int ix = (int)fx, iy = (int)fy, iz = (int)fz;
        float rx = wx - fx, ry = wy - fy, rz = wz - fz;

        #pragma unroll
        for (int c = 0; c < 8; c++) {
            int ax = ix + ((c >> 2) & 1);
            int ay = iy + ((c >> 1) & 1);
            int az = iz + (c & 1);
            float w = ((c & 4) ? rx : 1.0f - rx) *
                      ((c & 2) ? ry : 1.0f - ry) *
                      ((c & 1) ? rz : 1.0f - rz);
            if ((unsigned)ax < (unsigned)D && (unsigned)ay < (unsigned)D &&
                (unsigned)az < (unsigned)D) {
                sum += img[lin_idx<PERM>(ax, ay, az)] * w;
            }
        }
    }

    // warp-reduce line integral sum over all 96 samples
    #pragma unroll
    for (int o = 16; o > 0; o >>= 1)
        sum += __shfl_xor_sync(0xffffffffu, sum, o);

    // p = sum*seg*KW ; backprojected contribution per unit weight = p*seg*KW
    float a = seg * kw_const();
    float contrib = sum * a * a;

    // scatter: reuse cached voxel coords
    #pragma unroll
    for (int k = 0; k < 3; k++) {
        float wx = vX[k], wy = vY[k], wz = vZ[k];
        float fx = floorf(wx), fy = floorf(wy), fz = floorf(wz);
        int ix = (int)fx, iy = (int)fy, iz = (int)fz;
        float rx = wx - fx, ry = wy - fy, rz = wz - fz;

        #pragma unroll
        for (int c = 0; c < 8; c++) {
            int ax = ix + ((c >> 2) & 1);
            int ay = iy + ((c >> 1) & 1);
            int az = iz + (c & 1);
            float w = ((c & 4) ? rx : 1.0f - rx) *
                      ((c & 2) ? ry : 1.0f - ry) *
                      ((c & 1) ? rz : 1.0f - rz);
            if ((unsigned)ax < (unsigned)D && (unsigned)ay < (unsigned)D &&
                (unsigned)az < (unsigned)D) {
                atomicAdd(&acc[lin_idx<PERM>(ax, ay, az)], w * contrib);
            }
        }
    }
}

__global__ void zero_kernel(float4* __restrict__ out, int n4) {
    int i = blockIdx.x * blockDim.x + threadIdx.x;
    if (i < n4) out[i] = make_float4(0.f, 0.f, 0.f, 0.f);
}

__global__ void finalize_kernel(const float* __restrict__ img,
                                const float* __restrict__ eff,
                                float* __restrict__ out, int n) {
    int i = blockIdx.x * blockDim.x + threadIdx.x;
    if (i < n) {
        out[i] = img[i] / (eff[i] + 1e-8f) * out[i];
    }
}

extern "C" void kernel_launch(void* const* d_in, const int* in_sizes, int n_in,
                              void* d_out, int out_size) {
    const float* image  = (const float*)d_in[0];
    const float* eff    = (const float*)d_in[1];
    // d_in[2] = grid (int32[3]) — static dims, unused
    const float* center = (const float*)d_in[3];
    const float* size   = (const float*)d_in[4];
    const float* xlors  = (const float*)d_in[5];
    const float* ylors  = (const float*)d_in[6];
    const float* zlors  = (const float*)d_in[7];
    float* out = (float*)d_out;

    int nx = in_sizes[5] / 6;
    int ny = in_sizes[6] / 6;
    int nz = in_sizes[7] / 6;

    // zero the accumulator (d_out doubles as acc buffer)
    int n4 = out_size / 4;
    zero_kernel<<<(n4 + 255) / 256, 256>>>((float4*)out, n4);

    const int threads = NWARP_PER_BLK * 32;
    lor_kernel<0><<<(nz + NWARP_PER_BLK - 1) / NWARP_PER_BLK, threads>>>(
        zlors, image, center, size, out, nz);
    lor_kernel<1><<<(nx + NWARP_PER_BLK - 1) / NWARP_PER_BLK, threads>>>(
        xlors, image, center, size, out, nx);
    lor_kernel<2><<<(ny + NWARP_PER_BLK - 1) / NWARP_PER_BLK, threads>>>(
        ylors, image, center, size, out, ny);

    finalize_kernel<<<(out_size + 255) / 256, 256>>>(image, eff, out, out_size);
}

// round 2
// speedup vs baseline: 1.0449x; 1.0449x over previous
#include <cuda_runtime.h>
#include <math.h>

#define D 192
#define S_SAMPLES 96
#define NWARP_PER_BLK 8

static __device__ __forceinline__ float kw_const() { return 1.6925687506f; } // sqrt(9/pi)

// Vector reduction atomics (sm_90+)
static __device__ __forceinline__ void red_add_v2(float* addr, float a, float b) {
    asm volatile("red.global.add.v2.f32 [%0], {%1, %2};"
                 :: "l"(addr), "f"(a), "f"(b) : "memory");
}
static __device__ __forceinline__ void red_add_v4(float* addr, float a, float b, float c, float d) {
    asm volatile("red.global.add.v4.f32 [%0], {%1, %2, %3, %4};"
                 :: "l"(addr), "f"(a), "f"(b), "f"(c), "f"(d) : "memory");
}

// Decompose the permuted linear index (row, inner):
// PERM0: lin=(ix*D+iy)*D+iz  -> rows over (x,y), inner z
// PERM1: lin=(iy*D+iz)*D+ix  -> rows over (y,z), inner x
// PERM2: lin=(iy*D+ix)*D+iz  -> rows over (y,x), inner z
template<int PERM>
static __device__ __forceinline__ void decompose(
    float wx, float wy, float wz,
    int& i0, int& i1, int& iu, float& r0, float& r1, float& ru)
{
    float a0, a1, u;
    if (PERM == 0)      { a0 = wx; a1 = wy; u = wz; }
    else if (PERM == 1) { a0 = wy; a1 = wz; u = wx; }
    else                { a0 = wy; a1 = wx; u = wz; }
    float f0 = floorf(a0), f1 = floorf(a1), fu = floorf(u);
    i0 = (int)f0; i1 = (int)f1; iu = (int)fu;
    r0 = a0 - f0; r1 = a1 - f1; ru = u - fu;
}

template<int PERM>
static __device__ __forceinline__ float sample_gather(
    const float* __restrict__ img, float wx, float wy, float wz)
{
    int i0, i1, iu; float r0, r1, ru;
    decompose<PERM>(wx, wy, wz, i0, i1, iu, r0, r1, ru);
    float wu0 = 1.0f - ru, wu1 = ru;
    int o = iu & 3;
    bool pair_ok = (iu >= 0) && (iu < D - 1) && (o != 3);
    float sum = 0.0f;

    #pragma unroll
    for (int c = 0; c < 4; c++) {
        int j0 = i0 + (c >> 1);
        int j1 = i1 + (c & 1);
        if ((unsigned)j0 >= (unsigned)D || (unsigned)j1 >= (unsigned)D) continue;
        float wrow = ((c & 2) ? r0 : 1.0f - r0) * ((c & 1) ? r1 : 1.0f - r1);
        int row = j0 * D + j1;
        if (pair_ok) {
            const float4 v = *reinterpret_cast<const float4*>(img + row * D + (iu & ~3));
            float e0 = (o == 0) ? v.x : ((o == 1) ? v.y : v.z);
            float e1 = (o == 0) ? v.y : ((o == 1) ? v.z : v.w);
            sum += wrow * (e0 * wu0 + e1 * wu1);
        } else {
            if ((unsigned)iu < (unsigned)D)       sum += img[row * D + iu]     * (wrow * wu0);
            if ((unsigned)(iu + 1) < (unsigned)D) sum += img[row * D + iu + 1] * (wrow * wu1);
        }
    }
    return sum;
}

template<int PERM>
static __device__ __forceinline__ void sample_scatter(
    float* __restrict__ acc, float wx, float wy, float wz, float contrib)
{
    int i0, i1, iu; float r0, r1, ru;
    decompose<PERM>(wx, wy, wz, i0, i1, iu, r0, r1, ru);
    float wu0 = (1.0f - ru) * contrib, wu1 = ru * contrib;
    int o = iu & 3;
    bool in_pair = (iu >= 0) && (iu < D - 1);

    #pragma unroll
    for (int c = 0; c < 4; c++) {
        int j0 = i0 + (c >> 1);
        int j1 = i1 + (c & 1);
        if ((unsigned)j0 >= (unsigned)D || (unsigned)j1 >= (unsigned)D) continue;
        float wrow = ((c & 2) ? r0 : 1.0f - r0) * ((c & 1) ? r1 : 1.0f - r1);
        int row = j0 * D + j1;
        float a0v = wrow * wu0, a1v = wrow * wu1;
        if (in_pair && (o == 0 || o == 2)) {
            red_add_v2(acc + row * D + iu, a0v, a1v);
        } else if (in_pair && o == 1) {
            red_add_v4(acc + row * D + (iu & ~3), 0.0f, a0v, a1v, 0.0f);
        } else {
            if ((unsigned)iu < (unsigned)D)       atomicAdd(acc + row * D + iu,     a0v);
            if ((unsigned)(iu + 1) < (unsigned)D) atomicAdd(acc + row * D + iu + 1, a1v);
        }
    }
}

template<int PERM>
__global__ void __launch_bounds__(NWARP_PER_BLK * 32)
lor_kernel(const float* __restrict__ lors,
           const float* __restrict__ img,
           const float* __restrict__ center,
           const float* __restrict__ size,
           float* __restrict__ acc,
           int n)
{
    int warp = (blockIdx.x * blockDim.x + threadIdx.x) >> 5;
    int lane = threadIdx.x & 31;
    if (warp >= n) return;

    const float* L = lors + (size_t)warp * 6;
    float p1x = L[0], p1y = L[1], p1z = L[2];
    float p2x = L[3], p2y = L[4], p2z = L[5];

    float sx = size[0], sy = size[1], sz = size[2];
    float vszx = sx / (float)D, vszy = sy / (float)D, vszz = sz / (float)D;
    float ox = center[0] - 0.5f * sx, oy = center[1] - 0.5f * sy, oz = center[2] - 0.5f * sz;

    float dx = p2x - p1x, dy = p2y - p1y, dz = p2z - p1z;
    float seg = sqrtf(dx * dx + dy * dy + dz * dz) * (1.0f / (float)S_SAMPLES);

    float vX[3], vY[3], vZ[3];
    float sum = 0.0f;

    #pragma unroll
    for (int k = 0; k < 3; k++) {
        int s = lane + 32 * k;
        float t = ((float)s + 0.5f) * (1.0f / (float)S_SAMPLES);
        float wx = (p1x + t * dx - ox) / vszx - 0.5f;
        float wy = (p1y + t * dy - oy) / vszy - 0.5f;
        float wz = (p1z + t * dz - oz) / vszz - 0.5f;
        vX[k] = wx; vY[k] = wy; vZ[k] = wz;
        sum += sample_gather<PERM>(img, wx, wy, wz);
    }

    #pragma unroll
    for (int off = 16; off > 0; off >>= 1)
        sum += __shfl_xor_sync(0xffffffffu, sum, off);

    float a = seg * kw_const();
    float contrib = sum * a * a;

    #pragma unroll
    for (int k = 0; k < 3; k++)
        sample_scatter<PERM>(acc, vX[k], vY[k], vZ[k], contrib);
}

__global__ void zero_kernel(float4* __restrict__ out, int n4) {
    int i = blockIdx.x * blockDim.x + threadIdx.x;
    if (i < n4) out[i] = make_float4(0.f, 0.f, 0.f, 0.f);
}

__global__ void finalize_kernel(const float* __restrict__ img,
                                const float* __restrict__ eff,
                                float* __restrict__ out, int n) {
    int i = blockIdx.x * blockDim.x + threadIdx.x;
    if (i < n) out[i] = img[i] / (eff[i] + 1e-8f) * out[i];
}

extern "C" void kernel_launch(void* const* d_in, const int* in_sizes, int n_in,
                              void* d_out, int out_size) {
    const float* image  = (const float*)d_in[0];
    const float* eff    = (const float*)d_in[1];
    const float* center = (const float*)d_in[3];
    const float* size   = (const float*)d_in[4];
    const float* xlors  = (const float*)d_in[5];
    const float* ylors  = (const float*)d_in[6];
    const float* zlors  = (const float*)d_in[7];
    float* out = (float*)d_out;

    int nx = in_sizes[5] / 6;
    int ny = in_sizes[6] / 6;
    int nz = in_sizes[7] / 6;

    int n4 = out_size / 4;
    zero_kernel<<<(n4 + 255) / 256, 256>>>((float4*)out, n4);

    const int threads = NWARP_PER_BLK * 32;
    lor_kernel<0><<<(nz + NWARP_PER_BLK - 1) / NWARP_PER_BLK, threads>>>(
        zlors, image, center, size, out, nz);
    lor_kernel<1><<<(nx + NWARP_PER_BLK - 1) / NWARP_PER_BLK, threads>>>(
        xlors, image, center, size, out, nx);
    lor_kernel<2><<<(ny + NWARP_PER_BLK - 1) / NWARP_PER_BLK, threads>>>(
        ylors, image, center, size, out, ny);

    finalize_kernel<<<(out_size + 255) / 256, 256>>>(image, eff, out, out_size);
}